// round 17
// baseline (speedup 1.0000x reference)
#include <cuda_runtime.h>
#include <cuda_bf16.h>
#include <cooperative_groups.h>

namespace cg = cooperative_groups;

// Problem constants (fixed by the dataset builder)
#define BB    64          // batches
#define SS    4096        // spikes per batch
#define LL    25          // Lmax
#define NBINS 3600        // OH*OW
#define HBINS 1800        // bins per scatter half-warp task
#define CAPC  128         // cap
#define NC    64          // chunks per batch
#define CHUNK (SS / NC)   // 64 spikes per chunk
#define NSC   16          // superchunks of 256 spikes (4 chunks) for packed count
#define OFFCLAMP 160u     // offsets >= 128 are dead; clamp keeps u8 exact
#define FULLM 0xffffffffu

#define NBLK  1024        // BB*NSC == BB*NC*2/8 == 1024: one grid fits all phases
#define F4PB  7200        // float4 fill elements per block (1024*7200 = 29.5M floats/4)

// Scratch (static device globals — allocation-free per harness rules)
__device__ unsigned int  g_counts[BB * NSC * NBINS];          // 14.7 MB
__device__ unsigned char g_off[(size_t)BB * NC * NBINS];      // 14.7 MB, u8

// ---------------------------------------------------------------------------
// One cooperative kernel, three phases separated by grid.sync():
//  A: packed per-chunk histogram (block = superchunk) + fill slice of output
//     (count's L2 gathers/ATOMS overlap fill's DRAM writes inside each block)
//  B: exclusive scan over 64 chunks per (b,bin), u32-packed u8 offsets
//  C: ordered scatter, bin-half split (warp per (chunk,half)), u8 counters
// Shared buffer is a 14.4 KB union: hist u32[3600] in A, cnt u8[8][1800] in C.
// ---------------------------------------------------------------------------
__global__ void __launch_bounds__(256, 7)
fused_kernel(const int* __restrict__ spikes,
             const int* __restrict__ indices,
             float* __restrict__ out) {
    cg::grid_group grid = cg::this_grid();
    __shared__ __align__(16) unsigned char s_buf[4 * NBINS];   // 14400 B

    int tid = threadIdx.x;
    int warp = tid >> 5, lane = tid & 31;

    // ======================= Phase A: count + fill =========================
    {
        unsigned int* hist = (unsigned int*)s_buf;
        for (int i = tid; i < NBINS; i += 256) hist[i] = 0u;
        __syncthreads();

        int b  = blockIdx.x >> 4;   // NSC == 16
        int sc = blockIdx.x & 15;
        const int* sp = spikes + b * SS + sc * 256 + warp * 32;
        unsigned int add = 1u << (8 * (warp >> 1));

        for (int k = 0; k < 32; k++) {
            int id = __ldg(&sp[k]);                  // uniform broadcast load
            int j = -1;
            if (lane < LL) j = __ldg(&indices[id * LL + lane]);
            if (j >= 0) {
                unsigned int bin = (unsigned int)j % (unsigned int)NBINS;
                atomicAdd(&hist[bin], add);
            }
        }
        __syncthreads();

        unsigned int* dst = g_counts + (size_t)blockIdx.x * NBINS;
        for (int i = tid; i < NBINS; i += 256) dst[i] = hist[i];

        // Fill this block's slice of the output with -1.0f (streaming).
        float4 v = make_float4(-1.0f, -1.0f, -1.0f, -1.0f);
        float4* o4 = (float4*)out + (size_t)blockIdx.x * F4PB;
        for (int i = tid; i < F4PB; i += 256) __stcs(&o4[i], v);
    }

    grid.sync();

    // =========================== Phase B: scan =============================
    {
        int idx = blockIdx.x * 256 + tid;            // thread per 4 bins
        if (idx < BB * (NBINS / 4)) {
            int b  = idx / (NBINS / 4);
            int bq = idx - b * (NBINS / 4);
            int bin0 = bq * 4;
            unsigned int s0 = 0, s1 = 0, s2 = 0, s3 = 0;
#pragma unroll
            for (int sc = 0; sc < NSC; sc++) {
                const uint4* src = (const uint4*)(g_counts
                                   + ((size_t)(b * NSC + sc)) * NBINS + bin0);
                uint4 v = __ldg(src);
#pragma unroll
                for (int sub = 0; sub < 4; sub++) {
                    int c = sc * 4 + sub;
                    unsigned int w = min(s0, OFFCLAMP)
                                   | (min(s1, OFFCLAMP) << 8)
                                   | (min(s2, OFFCLAMP) << 16)
                                   | (min(s3, OFFCLAMP) << 24);
                    *(unsigned int*)(g_off
                        + ((size_t)(b * NC + c)) * NBINS + bin0) = w;
                    unsigned int sh = 8 * sub;
                    s0 += (v.x >> sh) & 0xFFu;
                    s1 += (v.y >> sh) & 0xFFu;
                    s2 += (v.z >> sh) & 0xFFu;
                    s3 += (v.w >> sh) & 0xFFu;
                }
            }
        }
    }

    grid.sync();

    // ========================== Phase C: scatter ===========================
    {
        unsigned char* cnt = s_buf;                  // 8 warps x 1800 u8
        int task = blockIdx.x * 8 + warp;            // 8192 tasks
        int chunk = task >> 1;
        int half  = task & 1;
        int b = chunk >> 6;        // NC == 64
        int c = chunk & 63;

        unsigned char* my = cnt + warp * HBINS;
        {
            const uint2* offv = (const uint2*)(g_off + (size_t)chunk * NBINS
                                                     + half * HBINS);
            uint2* myv = (uint2*)my;
            for (int i = lane; i < HBINS / 8; i += 32) myv[i] = __ldg(&offv[i]);
        }

        const int* sp = spikes + b * SS + c * CHUNK;
        int idlo = __ldg(&sp[lane]);
        int idhi = __ldg(&sp[32 + lane]);
        float* outb = out + (size_t)b * CAPC * NBINS;
        bool act = lane < LL;
        int lo = half * HBINS;
        __syncwarp();

        #define GATHER(dst, s) do {                                          \
            int _id = ((s) < 32) ? __shfl_sync(FULLM, idlo, (s))             \
                                 : __shfl_sync(FULLM, idhi, (s) - 32);       \
            (dst) = act ? __ldg(&indices[_id * LL + lane]) : -1;             \
        } while (0)

        #define PROCESS(jv) do {                                             \
            if ((jv) >= 0) {                                                 \
                unsigned int ju  = (unsigned int)(jv);                       \
                unsigned int ckk = ju / (unsigned int)NBINS;                 \
                unsigned int bin = ju - ckk * (unsigned int)NBINS;           \
                int bl = (int)bin - lo;                                      \
                if ((unsigned)bl < (unsigned)HBINS) {                        \
                    unsigned int r = my[bl];                                 \
                    my[bl] = (unsigned char)(r + 1u);                        \
                    if (r < CAPC)                                            \
                        outb[(size_t)r * NBINS + bin] = (float)ckk;          \
                }                                                            \
            }                                                                \
            __syncwarp();                                                    \
        } while (0)

        int a0, a1, a2, a3, b0, b1, b2, b3;
        GATHER(a0, 0); GATHER(a1, 1); GATHER(a2, 2); GATHER(a3, 3);
        GATHER(b0, 4); GATHER(b1, 5); GATHER(b2, 6); GATHER(b3, 7);

        #pragma unroll 4
        for (int g = 0; g < CHUNK / 4 - 2; g++) {
            int s = g * 4;
            int c0, c1, c2, c3;
            GATHER(c0, s + 8); GATHER(c1, s + 9);
            GATHER(c2, s + 10); GATHER(c3, s + 11);
            PROCESS(a0); PROCESS(a1); PROCESS(a2); PROCESS(a3);
            a0 = b0; a1 = b1; a2 = b2; a3 = b3;
            b0 = c0; b1 = c1; b2 = c2; b3 = c3;
        }
        PROCESS(a0); PROCESS(a1); PROCESS(a2); PROCESS(a3);
        PROCESS(b0); PROCESS(b1); PROCESS(b2); PROCESS(b3);

        #undef GATHER
        #undef PROCESS
    }
}

// ---------------------------------------------------------------------------
extern "C" void kernel_launch(void* const* d_in, const int* in_sizes, int n_in,
                              void* d_out, int out_size) {
    const int* spikes  = (const int*)d_in[0];   // (64, 4096, 1, 1) int32
    const int* indices = (const int*)d_in[1];   // (131072, 25) int32
    float* out = (float*)d_out;                 // (64, 128, 60, 60) float32

    void* args[3] = { (void*)&spikes, (void*)&indices, (void*)&out };
    cudaLaunchCooperativeKernel((const void*)fused_kernel,
                                dim3(NBLK), dim3(256), args, 0, 0);
}